// round 12
// baseline (speedup 1.0000x reference)
#include <cuda_runtime.h>
#include <cuda_fp16.h>
#include <math.h>
#include <stdint.h>

#define T_TOK 8192
#define HID   7168
#define NEXP  256

// ---- scratch ----
__device__ float g_part[2][(size_t)T_TOK * NEXP];   // 16 MB partial logits
__device__ int   g_nflag;
__device__ int   g_flags[T_TOK];

#define THETA   2e-5f
#define MARG_T  (3.0f * THETA)
#define MARG_G  (8.0f * THETA)

// ============================ helpers ============================
#define MMAH(d, a, b) asm volatile( \
    "mma.sync.aligned.m16n8k16.row.col.f32.f16.f16.f32 " \
    "{%0,%1,%2,%3}, {%4,%5,%6,%7}, {%8,%9}, {%0,%1,%2,%3};" \
    : "+f"((d)[0]), "+f"((d)[1]), "+f"((d)[2]), "+f"((d)[3]) \
    : "r"((a)[0]), "r"((a)[1]), "r"((a)[2]), "r"((a)[3]), \
      "r"((b)[0]), "r"((b)[1]))

__device__ __forceinline__ uint32_t pack_h2(__half a, __half b) {
    __half2 h2 = __halves2half2(a, b);
    __half2_raw r = *reinterpret_cast<__half2_raw*>(&h2);
    return (uint32_t)r.x | ((uint32_t)r.y << 16);
}
// split two floats -> packed hi-u32 and lo-u32 (round-to-nearest both)
__device__ __forceinline__ void split2(float x0, float x1, uint32_t& hi, uint32_t& lo) {
    __half h0 = __float2half_rn(x0), h1 = __float2half_rn(x1);
    __half l0 = __float2half_rn(x0 - __half2float(h0));
    __half l1 = __float2half_rn(x1 - __half2float(h1));
    hi = pack_h2(h0, h1);
    lo = pack_h2(l0, l1);
}

// ============================ K1 config ============================
constexpr int BM = 128, BN = 128, BK = 32;      // BK = fp32 k per chunk
constexpr int KSPLIT = 2;
constexpr int KHALF  = HID / KSPLIT;            // 3584
constexpr int NCHUNK = KHALF / BK;              // 112
constexpr int RS = 20;                          // u32 row stride (16 data + 4 pad)
constexpr int TILE_U = 128 * RS;                // 2560 u32
constexpr int STAGE_U = 4 * TILE_U;             // Ah Al Bh Bl = 40 KB
constexpr int SMEM_BYTES = 2 * STAGE_U * 4;     // 81920

// ============================================================================
// K1: fused-split fp16 3-pass GEMM, split-K x2, raw partial logits out.
//     cvt+STS of chunk c+1 overlaps MMA of chunk c; 2 CTAs/SM.
// ============================================================================
__global__ __launch_bounds__(256, 2) void gemm_f16_kernel(
    const float* __restrict__ x, const float* __restrict__ w)
{
    extern __shared__ uint32_t smem[];

    const int tid  = threadIdx.x;
    const int lane = tid & 31;
    const int wid  = tid >> 5;
    const int g    = lane >> 2;
    const int tg   = lane & 3;

    const int ks = blockIdx.x >> 7;             // 0/1 k-split
    const int r  = blockIdx.x & 127;
    const int n0 = (r & 1) * BN;
    const int m0 = (r >> 1) * BM;
    const int wm = (wid & 1) * 64;
    const int wn = (wid >> 1) * 32;
    const int k0 = ks * KHALF;

    // load mapping: row lrow of A and B, 16 consecutive k at lhalf*16
    const int lrow  = tid >> 1;
    const int lhalf = tid & 1;
    const float* ga = x + (size_t)(m0 + lrow) * HID + k0 + lhalf * 16;
    const float* gb = w + (size_t)(n0 + lrow) * HID + k0 + lhalf * 16;
    const int wbase = lrow * RS + lhalf * 8;    // u32 index within a tile

    float4 pa[4], pb[4];
    auto LOADC = [&](int c) {
        const float* a = ga + c * BK;
        const float* b = gb + c * BK;
#pragma unroll
        for (int q = 0; q < 4; ++q) {
            pa[q] = *(const float4*)(a + q * 4);
            pb[q] = *(const float4*)(b + q * 4);
        }
    };

    auto CVTSTS = [&](int s) {
        uint32_t* Ah = smem + s * STAGE_U;
        uint32_t* Al = Ah + TILE_U;
        uint32_t* Bh = Ah + 2 * TILE_U;
        uint32_t* Bl = Ah + 3 * TILE_U;
        uint4 uh, ul;
        split2(pa[0].x, pa[0].y, uh.x, ul.x);
        split2(pa[0].z, pa[0].w, uh.y, ul.y);
        split2(pa[1].x, pa[1].y, uh.z, ul.z);
        split2(pa[1].z, pa[1].w, uh.w, ul.w);
        *(uint4*)(Ah + wbase) = uh;
        *(uint4*)(Al + wbase) = ul;
        split2(pa[2].x, pa[2].y, uh.x, ul.x);
        split2(pa[2].z, pa[2].w, uh.y, ul.y);
        split2(pa[3].x, pa[3].y, uh.z, ul.z);
        split2(pa[3].z, pa[3].w, uh.w, ul.w);
        *(uint4*)(Ah + wbase + 4) = uh;
        *(uint4*)(Al + wbase + 4) = ul;
        split2(pb[0].x, pb[0].y, uh.x, ul.x);
        split2(pb[0].z, pb[0].w, uh.y, ul.y);
        split2(pb[1].x, pb[1].y, uh.z, ul.z);
        split2(pb[1].z, pb[1].w, uh.w, ul.w);
        *(uint4*)(Bh + wbase) = uh;
        *(uint4*)(Bl + wbase) = ul;
        split2(pb[2].x, pb[2].y, uh.x, ul.x);
        split2(pb[2].z, pb[2].w, uh.y, ul.y);
        split2(pb[3].x, pb[3].y, uh.z, ul.z);
        split2(pb[3].z, pb[3].w, uh.w, ul.w);
        *(uint4*)(Bh + wbase + 4) = uh;
        *(uint4*)(Bl + wbase + 4) = ul;
    };

    float acc[4][4][4];
#pragma unroll
    for (int i = 0; i < 4; ++i)
#pragma unroll
        for (int j = 0; j < 4; ++j)
#pragma unroll
            for (int e = 0; e < 4; ++e) acc[i][j][e] = 0.f;

    // prologue: chunk0 -> stage0; prefetch chunk1
    LOADC(0);
    CVTSTS(0);
    LOADC(1);
    __syncthreads();

#pragma unroll 1
    for (int c = 0; c < NCHUNK; ++c) {
        // stage c&1 holds chunk c; pa/pb hold chunk c+1
        if (c + 1 < NCHUNK) CVTSTS((c + 1) & 1);
        if (c + 2 < NCHUNK) LOADC(c + 2);

        const uint32_t* Ah = smem + (c & 1) * STAGE_U;
        const uint32_t* Al = Ah + TILE_U;
        const uint32_t* Bh = Ah + 2 * TILE_U;
        const uint32_t* Bl = Ah + 3 * TILE_U;

#pragma unroll
        for (int kk = 0; kk < 2; ++kk) {
            const int kb = kk * 8 + tg;
            uint32_t ah[4][4], al[4][4], bh[4][2], bl[4][2];
#pragma unroll
            for (int i = 0; i < 4; ++i) {
                const int r0 = (wm + i * 16 + g) * RS;
                const int r1 = (wm + i * 16 + g + 8) * RS;
                ah[i][0] = Ah[r0 + kb];     ah[i][1] = Ah[r1 + kb];
                ah[i][2] = Ah[r0 + kb + 4]; ah[i][3] = Ah[r1 + kb + 4];
                al[i][0] = Al[r0 + kb];     al[i][1] = Al[r1 + kb];
                al[i][2] = Al[r0 + kb + 4]; al[i][3] = Al[r1 + kb + 4];
            }
#pragma unroll
            for (int j = 0; j < 4; ++j) {
                const int rn = (wn + j * 8 + g) * RS;
                bh[j][0] = Bh[rn + kb]; bh[j][1] = Bh[rn + kb + 4];
                bl[j][0] = Bl[rn + kb]; bl[j][1] = Bl[rn + kb + 4];
            }
#pragma unroll
            for (int i = 0; i < 4; ++i)
#pragma unroll
                for (int j = 0; j < 4; ++j) {
                    MMAH(acc[i][j], ah[i], bh[j]);
                    MMAH(acc[i][j], ah[i], bl[j]);
                    MMAH(acc[i][j], al[i], bh[j]);
                }
        }
        __syncthreads();   // MMA(c) done (stage c&1 free) and STS(c+1) visible
    }

    // epilogue: raw partial logits
    float* plane = g_part[ks];
#pragma unroll
    for (int i = 0; i < 4; ++i) {
        const int r0 = m0 + wm + i * 16 + g;
#pragma unroll
        for (int j = 0; j < 4; ++j) {
            float* p0 = plane + (size_t)r0 * NEXP + n0 + wn + j * 8 + tg * 2;
            float* p1 = p0 + 8 * NEXP;
            *(float2*)p0 = make_float2(acc[i][j][0], acc[i][j][1]);
            *(float2*)p1 = make_float2(acc[i][j][2], acc[i][j][3]);
        }
    }
}

// ============================================================================
__global__ void reset_kernel() { g_nflag = 0; }

// ============================================================================
// K2: sum partials, sigmoid, margin-checked gate; flag tight tokens
// ============================================================================
__global__ __launch_bounds__(256) void gate_margin_kernel(
    const float* __restrict__ bias,
    float* __restrict__ out, int out_size)
{
    const int wid = threadIdx.x >> 5;
    const int l   = threadIdx.x & 31;
    const int t   = blockIdx.x * 8 + wid;

    const float* p0 = g_part[0] + (size_t)t * NEXP;
    const float* p1 = g_part[1] + (size_t)t * NEXP;
    float s[8], v[8];
#pragma unroll
    for (int k = 0; k < 8; ++k) {
        float logit = p0[k * 32 + l] + p1[k * 32 + l];
        s[k] = 1.f / (1.f + expf(-logit));
        v[k] = s[k] + bias[k * 32 + l];
    }

    float gsc[8];
#pragma unroll
    for (int k = 0; k < 8; ++k) {
        float m1 = v[k];
#pragma unroll
        for (int o = 16; o > 0; o >>= 1) m1 = fmaxf(m1, __shfl_xor_sync(0xffffffffu, m1, o));
        unsigned bal = __ballot_sync(0xffffffffu, v[k] == m1);
        int fl = __ffs(bal) - 1;
        float vx = (l == fl) ? -INFINITY : v[k];
#pragma unroll
        for (int o = 16; o > 0; o >>= 1) vx = fmaxf(vx, __shfl_xor_sync(0xffffffffu, vx, o));
        gsc[k] = m1 + vx;
    }

    unsigned keep = 0;
    float g4 = INFINITY;
#pragma unroll
    for (int r = 0; r < 4; ++r) {
        float best = -INFINITY; int bi = 0;
#pragma unroll
        for (int k = 0; k < 8; ++k) {
            bool tk = !((keep >> k) & 1u) && (gsc[k] > best);
            best = tk ? gsc[k] : best;
            bi   = tk ? k : bi;
        }
        keep |= 1u << bi;
        g4 = best;
    }
    float g5 = -INFINITY;
#pragma unroll
    for (int k = 0; k < 8; ++k)
        if (!((keep >> k) & 1u)) g5 = fmaxf(g5, gsc[k]);

    bool flag = (g4 - g5) < MARG_G;

    float cand[8];
#pragma unroll
    for (int k = 0; k < 8; ++k) cand[k] = ((keep >> k) & 1u) ? v[k] : -INFINITY;

    float sval[9]; int sel[9];
#pragma unroll
    for (int r = 0; r < 9; ++r) {
        float bv = cand[0]; int bk = 0;
#pragma unroll
        for (int k = 1; k < 8; ++k) {
            bool tk = cand[k] > bv;
            bv = tk ? cand[k] : bv;
            bk = tk ? k : bk;
        }
        int be = bk * 32 + l;
#pragma unroll
        for (int o = 16; o > 0; o >>= 1) {
            float ov = __shfl_xor_sync(0xffffffffu, bv, o);
            int   oe = __shfl_xor_sync(0xffffffffu, be, o);
            if (ov > bv || (ov == bv && oe < be)) { bv = ov; be = oe; }
        }
        sval[r] = bv; sel[r] = be;
        const int kk = be >> 5, ll = be & 31;
#pragma unroll
        for (int k = 0; k < 8; ++k)
            if (k == kk && l == ll) cand[k] = -INFINITY;
    }
#pragma unroll
    for (int r = 0; r < 8; ++r)
        flag = flag || ((sval[r] - sval[r + 1]) < MARG_T);

    float wv[8];
#pragma unroll
    for (int r = 0; r < 8; ++r) {
        const int kk = sel[r] >> 5, ll = sel[r] & 31;
        float val = 0.f;
#pragma unroll
        for (int k = 0; k < 8; ++k)
            if (k == kk) val = s[k];
        wv[r] = __shfl_sync(0xffffffffu, val, ll);
    }

    if (l == 0) {
        if (flag) {
            int idx = atomicAdd(&g_nflag, 1);
            g_flags[idx] = t;
        }
        float sw = 0.f;
#pragma unroll
        for (int r = 0; r < 8; ++r) sw += wv[r];
        const float inv = 2.5f / (sw + 1e-20f);
        float4 w0 = make_float4(wv[0] * inv, wv[1] * inv, wv[2] * inv, wv[3] * inv);
        float4 w1 = make_float4(wv[4] * inv, wv[5] * inv, wv[6] * inv, wv[7] * inv);
        float4* wo = (float4*)(out + (size_t)t * 8);
        wo[0] = w0; wo[1] = w1;
        if (out_size >= 2 * T_TOK * 8) {
            float4 i0 = make_float4((float)sel[0], (float)sel[1], (float)sel[2], (float)sel[3]);
            float4 i1 = make_float4((float)sel[4], (float)sel[5], (float)sel[6], (float)sel[7]);
            float4* io = (float4*)(out + (size_t)T_TOK * 8 + (size_t)t * 8);
            io[0] = i0; io[1] = i1;
        }
    }
}

// ============================================================================
// K3: exact serial recompute + gate for flagged tokens (ascending-k chain)
// ============================================================================
__global__ __launch_bounds__(256) void fixup_kernel(
    const float* __restrict__ x, const float* __restrict__ w,
    const float* __restrict__ bias,
    float* __restrict__ out, int out_size)
{
    __shared__ float xs[HID];
    __shared__ float ss[NEXP];

    const int tid = threadIdx.x;
    const int nflag = g_nflag;

    for (int fi = blockIdx.x; fi < nflag; fi += gridDim.x) {
        const int t = g_flags[fi];

        for (int i = tid; i < HID; i += 256)
            xs[i] = x[(size_t)t * HID + i];
        __syncthreads();

        {
            const float4* wr = (const float4*)(w + (size_t)tid * HID);
            float acc = 0.f;
#pragma unroll 8
            for (int q = 0; q < HID / 4; ++q) {
                float4 f = wr[q];
                const float* xq = xs + q * 4;
                acc = fmaf(xq[0], f.x, acc);
                acc = fmaf(xq[1], f.y, acc);
                acc = fmaf(xq[2], f.z, acc);
                acc = fmaf(xq[3], f.w, acc);
            }
            ss[tid] = 1.f / (1.f + expf(-acc));
        }
        __syncthreads();

        if (tid < 32) {
            const int l = tid;
            float v[8];
#pragma unroll
            for (int k = 0; k < 8; ++k)
                v[k] = ss[k * 32 + l] + bias[k * 32 + l];

            float gsc[8];
#pragma unroll
            for (int k = 0; k < 8; ++k) {
                float m1 = v[k];
#pragma unroll
                for (int o = 16; o > 0; o >>= 1) m1 = fmaxf(m1, __shfl_xor_sync(0xffffffffu, m1, o));
                unsigned bal = __ballot_sync(0xffffffffu, v[k] == m1);
                int fl = __ffs(bal) - 1;
                float vx = (l == fl) ? -INFINITY : v[k];
#pragma unroll
                for (int o = 16; o > 0; o >>= 1) vx = fmaxf(vx, __shfl_xor_sync(0xffffffffu, vx, o));
                gsc[k] = m1 + vx;
            }
            unsigned keep = 0;
#pragma unroll
            for (int r = 0; r < 4; ++r) {
                float best = -INFINITY; int bi = 0;
#pragma unroll
                for (int k = 0; k < 8; ++k) {
                    bool tk = !((keep >> k) & 1u) && (gsc[k] > best);
                    best = tk ? gsc[k] : best;
                    bi   = tk ? k : bi;
                }
                keep |= 1u << bi;
            }
            float cand[8];
#pragma unroll
            for (int k = 0; k < 8; ++k) cand[k] = ((keep >> k) & 1u) ? v[k] : -INFINITY;

            int sel[8]; float wv[8];
#pragma unroll
            for (int r = 0; r < 8; ++r) {
                float bv = cand[0]; int bk = 0;
#pragma unroll
                for (int k = 1; k < 8; ++k) {
                    bool tk = cand[k] > bv;
                    bv = tk ? cand[k] : bv;
                    bk = tk ? k : bk;
                }
                int be = bk * 32 + l;
#pragma unroll
                for (int o = 16; o > 0; o >>= 1) {
                    float ov = __shfl_xor_sync(0xffffffffu, bv, o);
                    int   oe = __shfl_xor_sync(0xffffffffu, be, o);
                    if (ov > bv || (ov == bv && oe < be)) { bv = ov; be = oe; }
                }
                sel[r] = be;
                const int kk = be >> 5, ll = be & 31;
#pragma unroll
                for (int k = 0; k < 8; ++k)
                    if (k == kk && l == ll) cand[k] = -INFINITY;
            }
            if (l == 0) {
                float sw = 0.f;
#pragma unroll
                for (int r = 0; r < 8; ++r) { wv[r] = ss[sel[r]]; sw += wv[r]; }
                const float inv = 2.5f / (sw + 1e-20f);
                float* wo = out + (size_t)t * 8;
#pragma unroll
                for (int r = 0; r < 8; ++r) wo[r] = wv[r] * inv;
                if (out_size >= 2 * T_TOK * 8) {
                    float* io = out + (size_t)T_TOK * 8 + (size_t)t * 8;
#pragma unroll
                    for (int r = 0; r < 8; ++r) io[r] = (float)sel[r];
                }
            }
        }
        __syncthreads();
    }
}

// ============================================================================
extern "C" void kernel_launch(void* const* d_in, const int* in_sizes, int n_in,
                              void* d_out, int out_size)
{
    const float* x = nullptr; const float* w = nullptr; const float* b = nullptr;
    for (int i = 0; i < n_in; ++i) {
        long long sz = in_sizes[i];
        if (sz == (long long)T_TOK * HID) x = (const float*)d_in[i];
        else if (sz == (long long)NEXP * HID) w = (const float*)d_in[i];
        else if (sz == NEXP) b = (const float*)d_in[i];
    }
    float* out = (float*)d_out;

    cudaFuncSetAttribute(gemm_f16_kernel,
                         cudaFuncAttributeMaxDynamicSharedMemorySize, SMEM_BYTES);

    reset_kernel<<<1, 1>>>();
    gemm_f16_kernel<<<128 * KSPLIT, 256, SMEM_BYTES>>>(x, w);
    gate_margin_kernel<<<T_TOK / 8, 256>>>(b, out, out_size);
    fixup_kernel<<<256, 256>>>(x, w, b, out, out_size);
}